// round 2
// baseline (speedup 1.0000x reference)
#include <cuda_runtime.h>
#include <cuda_bf16.h>
#include <math.h>

#define N_NODES 50000
#define N_EDGES 800000
#define HIDDEN 64
#define HD 64           // HEADS*ADIM
#define CLAMP_V 5.0f

// ---------------- scratch (device globals; no allocations allowed) ----------------
__device__ float g_qkv[N_NODES * 192];        // [Q(64) | K(64) | V(64)] per node
__device__ float g_score[N_EDGES * 8];        // clipped raw scores per (edge, head)
__device__ int   g_nodemax[N_NODES * 8];      // float bits of (score+5) via atomicMax
__device__ int   g_deg[N_NODES];
__device__ int   g_rowstart[N_NODES + 1];
__device__ int   g_cursor[N_NODES];
__device__ int   g_edgelist[N_EDGES];

// ---------------- zero scratch ----------------
__global__ void zero_kernel() {
    int i = blockIdx.x * blockDim.x + threadIdx.x;
    if (i < N_NODES * 8) g_nodemax[i] = 0;       // decodes to max = -CLAMP for empty
    if (i < N_NODES) { g_deg[i] = 0; g_cursor[i] = 0; }
}

// ---------------- QKV GEMM: 96-column tiles, 16 nodes per block ----------------
#define NPB 16
__global__ __launch_bounds__(96) void qkv_kernel(const float* __restrict__ x,
                                                 const float* __restrict__ W,
                                                 const float* __restrict__ bias,
                                                 int colbase) {
    __shared__ float sWT[64 * 97];      // sWT[k*97 + j] = W[colbase+j][k]
    __shared__ float sx[NPB * 64];
    int t = threadIdx.x;
    int n0 = blockIdx.x * NPB;

    for (int idx = t; idx < 96 * 64; idx += 96) {
        int j = idx >> 6, k = idx & 63;
        sWT[k * 97 + j] = W[(size_t)colbase * 64 + idx];   // == W[(colbase+j)*64 + k]
    }
    for (int idx = t; idx < NPB * 64; idx += 96)
        sx[idx] = x[(size_t)n0 * 64 + idx];
    __syncthreads();

    float acc[NPB];
#pragma unroll
    for (int i = 0; i < NPB; i++) acc[i] = 0.f;

#pragma unroll
    for (int k4 = 0; k4 < 16; k4++) {
        float w0 = sWT[(4 * k4 + 0) * 97 + t];
        float w1 = sWT[(4 * k4 + 1) * 97 + t];
        float w2 = sWT[(4 * k4 + 2) * 97 + t];
        float w3 = sWT[(4 * k4 + 3) * 97 + t];
#pragma unroll
        for (int i = 0; i < NPB; i++) {
            float4 c4 = *reinterpret_cast<const float4*>(&sx[i * 64 + 4 * k4]);
            acc[i] = fmaf(c4.x, w0, fmaf(c4.y, w1, fmaf(c4.z, w2, fmaf(c4.w, w3, acc[i]))));
        }
    }
    float b = bias[colbase + t];
#pragma unroll
    for (int i = 0; i < NPB; i++)
        g_qkv[(size_t)(n0 + i) * 192 + colbase + t] = acc[i] + b;
}

// ---------------- CSR build ----------------
__global__ void count_kernel(const int* __restrict__ eidx) {
    int e = blockIdx.x * blockDim.x + threadIdx.x;
    if (e < N_EDGES) atomicAdd(&g_deg[eidx[e]], 1);
}

__global__ __launch_bounds__(1024) void scan_kernel() {
    __shared__ int warp_sums[32];
    __shared__ int s_carry;
    int t = threadIdx.x, lane = t & 31, wid = t >> 5;
    if (t == 0) s_carry = 0;
    __syncthreads();
    for (int base = 0; base < N_NODES; base += 1024) {
        int idx = base + t;
        int v = (idx < N_NODES) ? g_deg[idx] : 0;
        int x = v;
#pragma unroll
        for (int off = 1; off < 32; off <<= 1) {
            int y = __shfl_up_sync(0xffffffffu, x, off);
            if (lane >= off) x += y;
        }
        if (lane == 31) warp_sums[wid] = x;
        __syncthreads();
        if (wid == 0) {
            int s = warp_sums[lane];
#pragma unroll
            for (int off = 1; off < 32; off <<= 1) {
                int y = __shfl_up_sync(0xffffffffu, s, off);
                if (lane >= off) s += y;
            }
            warp_sums[lane] = s;
        }
        __syncthreads();
        int warp_off = (wid > 0) ? warp_sums[wid - 1] : 0;
        int incl = x + warp_off;
        int carry = s_carry;
        if (idx < N_NODES) g_rowstart[idx] = carry + incl - v;
        __syncthreads();
        if (t == 0) s_carry = carry + warp_sums[31];
        __syncthreads();
    }
    if (t == 0) g_rowstart[N_NODES] = s_carry;
}

__global__ void scatter_kernel(const int* __restrict__ eidx) {
    int e = blockIdx.x * blockDim.x + threadIdx.x;
    if (e < N_EDGES) {
        int d = eidx[e];
        int p = atomicAdd(&g_cursor[d], 1);
        g_edgelist[g_rowstart[d] + p] = e;
    }
}

// ---------------- fused edge kernel: E GEMM + conn + score + segment-max ----------------
#define EPB 16
__global__ __launch_bounds__(128) void edge_kernel(const float* __restrict__ cf,
                                                   const int* __restrict__ eidx,
                                                   const float* __restrict__ Ew_g,
                                                   const float* __restrict__ Eb_g,
                                                   const float* __restrict__ Aw,
                                                   float* __restrict__ conn_out) {
    __shared__ float sbuf[64 * 129];    // WT stage, later reused as Ew/Eb
    __shared__ float scf[EPB * 64];
    __shared__ int sdst[EPB], ssrc[EPB];
    __shared__ float sAw[64];
    int t = threadIdx.x;
    size_t e0 = (size_t)blockIdx.x * EPB;

    // stage W^T: sbuf[k*129 + j] = Ew_g[j*64 + k]
    for (int idx = t; idx < 128 * 64; idx += 128) {
        int j = idx >> 6, k = idx & 63;
        sbuf[k * 129 + j] = Ew_g[idx];
    }
    for (int idx = t; idx < EPB * 64; idx += 128)
        scf[idx] = cf[e0 * 64 + idx];
    if (t < EPB) { sdst[t] = eidx[e0 + t]; ssrc[t] = eidx[N_EDGES + e0 + t]; }
    if (t < 64) sAw[t] = Aw[t];
    __syncthreads();

    float acc[EPB];
#pragma unroll
    for (int i = 0; i < EPB; i++) acc[i] = 0.f;

#pragma unroll
    for (int k4 = 0; k4 < 16; k4++) {
        float w0 = sbuf[(4 * k4 + 0) * 129 + t];
        float w1 = sbuf[(4 * k4 + 1) * 129 + t];
        float w2 = sbuf[(4 * k4 + 2) * 129 + t];
        float w3 = sbuf[(4 * k4 + 3) * 129 + t];
#pragma unroll
        for (int i = 0; i < EPB; i++) {
            float4 c4 = *reinterpret_cast<const float4*>(&scf[i * 64 + 4 * k4]);
            acc[i] = fmaf(c4.x, w0, fmaf(c4.y, w1, fmaf(c4.z, w2, fmaf(c4.w, w3, acc[i]))));
        }
    }
    float bias = Eb_g[t];
    __syncthreads();   // done reading sWT

    // thread t holds Eh[i][t]; t<64 => Ew column, t>=64 => Eb column
    float* sEw = sbuf;
    float* sEb = sbuf + EPB * 64;
    {
        int c = t & 63;
        float* dstp = (t < 64) ? sEw : sEb;
#pragma unroll
        for (int i = 0; i < EPB; i++) dstp[i * 64 + c] = acc[i] + bias;
    }
    __syncthreads();

    // conn + score (+ atomic segment-max)
    for (int idx = t; idx < EPB * 64; idx += 128) {
        int i = idx >> 6, c = idx & 63;
        size_t e = e0 + i;
        int dn = sdst[i], sn = ssrc[i];
        float q = g_qkv[(size_t)dn * 192 + c];
        float kk = g_qkv[(size_t)sn * 192 + 64 + c];
        float c1 = (q + kk) * sEw[i * 64 + c];
        float c2 = (c1 > 0.f) ? sqrtf(c1) : ((c1 < 0.f) ? -sqrtf(-c1) : 0.f);
        float cn = c2 + sEb[i * 64 + c];
        cn = cn > 0.f ? cn : 0.f;
        conn_out[e * 64 + c] = cn;

        float p = cn * sAw[(c & 7) * 8 + (c >> 3)];
        p += __shfl_xor_sync(0xffffffffu, p, 1);
        p += __shfl_xor_sync(0xffffffffu, p, 2);
        p += __shfl_xor_sync(0xffffffffu, p, 4);
        if ((c & 7) == 0) {
            float s = fminf(fmaxf(p, -CLAMP_V), CLAMP_V);
            g_score[e * 8 + (c >> 3)] = s;
            atomicMax(&g_nodemax[(size_t)dn * 8 + (c >> 3)], __float_as_int(s + CLAMP_V));
        }
    }
}

// ---------------- node aggregation: softmax-weighted sums + Bw mix ----------------
__global__ __launch_bounds__(64) void node_kernel(const int* __restrict__ eidx,
                                                  const float* __restrict__ conn,
                                                  const float* __restrict__ Bw,
                                                  float* __restrict__ out) {
    __shared__ float sC[64];
    __shared__ float sBw[512];
    int n = blockIdx.x, t = threadIdx.x, h = t >> 3;
    for (int i = t; i < 512; i += 64) sBw[i] = Bw[i];

    int start = g_rowstart[n], end = g_rowstart[n + 1];
    float m = __int_as_float(g_nodemax[n * 8 + h]) - CLAMP_V;
    float aggV = 0.f, aggC = 0.f, sumw = 0.f;
    for (int idx = start; idx < end; ++idx) {
        int e = g_edgelist[idx];
        float s = g_score[(size_t)e * 8 + h];
        float w = __expf(s - m);
        int sn = eidx[N_EDGES + e];
        float v = g_qkv[(size_t)sn * 192 + 128 + t];
        float cn = conn[(size_t)e * 64 + t];
        aggV = fmaf(v, w, aggV);
        aggC = fmaf(cn, w, aggC);
        sumw += w;
    }
    sC[t] = aggC;
    __syncthreads();
    float rv = 0.f;
#pragma unroll
    for (int d2 = 0; d2 < 8; d2++)
        rv = fmaf(sC[h * 8 + d2], sBw[d2 * 64 + t], rv);
    out[(size_t)n * 64 + t] = (aggV + rv) / (sumw + 1e-16f);
}

// ---------------- launch ----------------
extern "C" void kernel_launch(void* const* d_in, const int* in_sizes, int n_in,
                              void* d_out, int out_size) {
    const float* x        = (const float*)d_in[0];
    const float* cf       = (const float*)d_in[1];
    const int*   eidx     = (const int*)d_in[2];
    const float* qkv_w    = (const float*)d_in[3];
    const float* qkv_b    = (const float*)d_in[4];
    const float* E_w      = (const float*)d_in[5];
    const float* E_b      = (const float*)d_in[6];
    const float* Aw       = (const float*)d_in[7];
    const float* Bw       = (const float*)d_in[8];

    float* out_No   = (float*)d_out;                       // [N, 64]
    float* out_conn = (float*)d_out + (size_t)N_NODES * 64; // [E, 64]

    zero_kernel<<<(N_NODES * 8 + 255) / 256, 256>>>();

    qkv_kernel<<<N_NODES / NPB, 96>>>(x, qkv_w, qkv_b, 0);
    qkv_kernel<<<N_NODES / NPB, 96>>>(x, qkv_w, qkv_b, 96);

    count_kernel<<<(N_EDGES + 255) / 256, 256>>>(eidx);
    scan_kernel<<<1, 1024>>>();
    scatter_kernel<<<(N_EDGES + 255) / 256, 256>>>(eidx);

    edge_kernel<<<N_EDGES / EPB, 128>>>(cf, eidx, E_w, E_b, Aw, out_conn);

    node_kernel<<<N_NODES, 64>>>(eidx, out_conn, Bw, out_No);
}